// round 1
// baseline (speedup 1.0000x reference)
#include <cuda_runtime.h>
#include <math.h>

#define NN   100000
#define DD   128
#define DFFN 512

// ---------------- scratch (device globals: allocation-free) ----------------
__device__ float g_Q[(size_t)NN * 128];        // Q,  col = h*32+k
__device__ float g_K[(size_t)5 * NN * 128];    // K_r, r-major slabs
__device__ float g_V[(size_t)5 * NN * 128];    // V_r
__device__ float g_E[(size_t)NN * 20];         // exp(logit) per (n, h*5+r)
__device__ float g_H[(size_t)NN * 128];        // post-LN1 hidden
__device__ float g_F[(size_t)NN * 512];        // FFN intermediate
__device__ float g_denom[20];                  // softmax denominators per (h,r)

// ---------------- zero denominators (runs every replay) ----------------
__global__ void zero_denoms_kernel() {
    if (threadIdx.x < 20) g_denom[threadIdx.x] = 0.0f;
}

// ---------------- generic 128x128 tile GEMM, 8x8 micro-tiles ----------------
// C[gr, cg] = sum_k A[rowmap(gr), k] * B[k, cg]
// B element (k, c) at: Bbase + z*BzStride + (c>>5)*HS + k*KS + (c&31)
// epi: 0 = plain store, 1 = bias+relu store, 2 = bias+resid+LayerNorm store
__global__ __launch_bounds__(256, 2)
void gemm_kernel(const float* __restrict__ A, int Astride,
                 const int* __restrict__ nbr,            // non-null -> gather, r = blockIdx.z
                 const float* __restrict__ Bbase, int HS, int KS, int BzStride,
                 int kchunks,
                 float* __restrict__ C, int Cstride, size_t CzStride,
                 int epi,
                 const float* __restrict__ bias,
                 const float* __restrict__ resid,
                 const float* __restrict__ gamma,
                 const float* __restrict__ beta)
{
    extern __shared__ float sm[];
    float* sA = sm;                 // [32][132] (k-major, padded)
    float* sB = sm + 32 * 132;      // [32][128]
    __shared__ int rowg[128];

    const int tid = threadIdx.x;
    const int tr  = tid >> 4;       // 0..15
    const int tc  = tid & 15;       // 0..15
    const int z   = blockIdx.z;
    const int cg0 = blockIdx.y * 128;
    const float* Bp = Bbase + (size_t)z * BzStride;
    float*       Cp = C + (size_t)z * CzStride;

    if (tid < 128) {
        int gr  = blockIdx.x * 128 + tid;
        int idx = (gr < NN) ? gr : (NN - 1);
        if (nbr != nullptr && z > 0 && gr < NN) idx = nbr[gr * 4 + (z - 1)];
        rowg[tid] = idx;
    }
    __syncthreads();

    float acc[8][8];
#pragma unroll
    for (int i = 0; i < 8; i++)
#pragma unroll
        for (int j = 0; j < 8; j++) acc[i][j] = 0.0f;

    for (int kc = 0; kc < kchunks; ++kc) {
        const int kg0 = kc * 32;
        // A tile: 128 rows x 32 k  (transpose into k-major smem)
#pragma unroll
        for (int p = 0; p < 4; ++p) {
            int idx = tid + p * 256;
            int row = idx >> 3;
            int kq  = (idx & 7) << 2;
            const float* src = A + (size_t)rowg[row] * Astride + kg0 + kq;
            float4 v = *(const float4*)src;
            sA[(kq + 0) * 132 + row] = v.x;
            sA[(kq + 1) * 132 + row] = v.y;
            sA[(kq + 2) * 132 + row] = v.z;
            sA[(kq + 3) * 132 + row] = v.w;
        }
        // B tile: 32 k x 128 c
#pragma unroll
        for (int p = 0; p < 4; ++p) {
            int i  = tid + p * 256;
            int kl = i >> 5;
            int c  = (i & 31) << 2;
            int cg = cg0 + c;
            const float* src = Bp + (size_t)(cg >> 5) * HS + (size_t)(kg0 + kl) * KS + (cg & 31);
            *(float4*)(sB + kl * 128 + c) = *(const float4*)src;
        }
        __syncthreads();
#pragma unroll 8
        for (int k = 0; k < 32; ++k) {
            float4 a0 = *(const float4*)(sA + k * 132 + tr * 8);
            float4 a1 = *(const float4*)(sA + k * 132 + tr * 8 + 4);
            float4 b0 = *(const float4*)(sB + k * 128 + tc * 8);
            float4 b1 = *(const float4*)(sB + k * 128 + tc * 8 + 4);
            float av[8] = {a0.x, a0.y, a0.z, a0.w, a1.x, a1.y, a1.z, a1.w};
            float bv[8] = {b0.x, b0.y, b0.z, b0.w, b1.x, b1.y, b1.z, b1.w};
#pragma unroll
            for (int i = 0; i < 8; i++)
#pragma unroll
                for (int j = 0; j < 8; j++)
                    acc[i][j] = fmaf(av[i], bv[j], acc[i][j]);
        }
        __syncthreads();
    }

    if (epi == 0) {
#pragma unroll
        for (int i = 0; i < 8; i++) {
            int gr = blockIdx.x * 128 + tr * 8 + i;
            if (gr < NN) {
                float* dst = Cp + (size_t)gr * Cstride + cg0 + tc * 8;
                *(float4*)(dst)     = make_float4(acc[i][0], acc[i][1], acc[i][2], acc[i][3]);
                *(float4*)(dst + 4) = make_float4(acc[i][4], acc[i][5], acc[i][6], acc[i][7]);
            }
        }
    } else if (epi == 1) {
        float bv[8];
#pragma unroll
        for (int j = 0; j < 8; j++) bv[j] = bias[cg0 + tc * 8 + j];
#pragma unroll
        for (int i = 0; i < 8; i++) {
            int gr = blockIdx.x * 128 + tr * 8 + i;
            if (gr < NN) {
                float o[8];
#pragma unroll
                for (int j = 0; j < 8; j++) o[j] = fmaxf(acc[i][j] + bv[j], 0.0f);
                float* dst = Cp + (size_t)gr * Cstride + cg0 + tc * 8;
                *(float4*)(dst)     = make_float4(o[0], o[1], o[2], o[3]);
                *(float4*)(dst + 4) = make_float4(o[4], o[5], o[6], o[7]);
            }
        }
    } else {
        // epi 2: t = acc + bias + resid, then row LayerNorm, store to Cp
        float* sC = sm;    // reuse: [128][132]
        float bv[8];
#pragma unroll
        for (int j = 0; j < 8; j++) bv[j] = bias[cg0 + tc * 8 + j];
#pragma unroll
        for (int i = 0; i < 8; i++) {
            int row = tr * 8 + i;
            const float* rp = resid + (size_t)rowg[row] * 128 + cg0 + tc * 8;
#pragma unroll
            for (int j = 0; j < 8; j++)
                sC[row * 132 + tc * 8 + j] = acc[i][j] + bv[j] + rp[j];
        }
        __syncthreads();
        int warp = tid >> 5, lane = tid & 31;
        for (int rr = warp; rr < 128; rr += 8) {
            int gr = blockIdx.x * 128 + rr;
            float v0 = sC[rr * 132 + lane];
            float v1 = sC[rr * 132 + 32 + lane];
            float v2 = sC[rr * 132 + 64 + lane];
            float v3 = sC[rr * 132 + 96 + lane];
            float s1 = v0 + v1 + v2 + v3;
            float s2 = v0 * v0 + v1 * v1 + v2 * v2 + v3 * v3;
#pragma unroll
            for (int o = 16; o > 0; o >>= 1) {
                s1 += __shfl_xor_sync(0xffffffffu, s1, o);
                s2 += __shfl_xor_sync(0xffffffffu, s2, o);
            }
            float mu  = s1 * (1.0f / 128.0f);
            float var = s2 * (1.0f / 128.0f) - mu * mu;
            float rs  = rsqrtf(var + 1e-5f);
            if (gr < NN) {
                float* dst = Cp + (size_t)gr * 128;
                dst[lane]      = (v0 - mu) * rs * gamma[lane]      + beta[lane];
                dst[lane + 32] = (v1 - mu) * rs * gamma[lane + 32] + beta[lane + 32];
                dst[lane + 64] = (v2 - mu) * rs * gamma[lane + 64] + beta[lane + 64];
                dst[lane + 96] = (v3 - mu) * rs * gamma[lane + 96] + beta[lane + 96];
            }
        }
    }
}

// ---------------- logits: S[h,n,r] = Q.K/sqrt(32); e = exp(S); denom += e ----
__global__ void logits_kernel() {
    __shared__ float sden[20];
    const int tid = threadIdx.x;
    if (tid < 20) sden[tid] = 0.0f;
    __syncthreads();
    const int n    = blockIdx.x * 8 + (tid >> 5);
    const int lane = tid & 31;
    if (n < NN) {
        const float scale = 0.1767766952966369f;   // 1/sqrt(32)
#pragma unroll
        for (int h = 0; h < 4; h++) {
            float q = g_Q[(size_t)n * 128 + h * 32 + lane];
#pragma unroll
            for (int r = 0; r < 5; r++) {
                float s = q * g_K[((size_t)r * NN + n) * 128 + h * 32 + lane];
#pragma unroll
                for (int o = 16; o > 0; o >>= 1) s += __shfl_xor_sync(0xffffffffu, s, o);
                float e = expf(s * scale);
                if (lane == 0) {
                    g_E[(size_t)n * 20 + h * 5 + r] = e;
                    atomicAdd(&sden[h * 5 + r], e);
                }
            }
        }
    }
    __syncthreads();
    if (tid < 20) atomicAdd(&g_denom[tid], sden[tid]);
}

// ---------------- combine: Z = sum_r (e/denom)*V_r ; h = LN(x + Z) ----------
__global__ void combine_ln1_kernel(const float* __restrict__ x,
                                   const float* __restrict__ g1,
                                   const float* __restrict__ be1) {
    __shared__ float sinv[20];
    const int tid = threadIdx.x;
    if (tid < 20) sinv[tid] = 1.0f / g_denom[tid];
    __syncthreads();
    const int n    = blockIdx.x * 8 + (tid >> 5);
    const int lane = tid & 31;
    if (n >= NN) return;
    float t[4];
    float s1 = 0.0f, s2 = 0.0f;
#pragma unroll
    for (int h = 0; h < 4; h++) {
        float z = 0.0f;
#pragma unroll
        for (int r = 0; r < 5; r++) {
            float p = g_E[(size_t)n * 20 + h * 5 + r] * sinv[h * 5 + r];
            z = fmaf(p, g_V[((size_t)r * NN + n) * 128 + h * 32 + lane], z);
        }
        float v = x[(size_t)n * 128 + h * 32 + lane] + z;
        t[h] = v;
        s1 += v;
        s2 = fmaf(v, v, s2);
    }
#pragma unroll
    for (int o = 16; o > 0; o >>= 1) {
        s1 += __shfl_xor_sync(0xffffffffu, s1, o);
        s2 += __shfl_xor_sync(0xffffffffu, s2, o);
    }
    float mu  = s1 * (1.0f / 128.0f);
    float var = s2 * (1.0f / 128.0f) - mu * mu;
    float rs  = rsqrtf(var + 1e-5f);
#pragma unroll
    for (int h = 0; h < 4; h++) {
        int c = h * 32 + lane;
        g_H[(size_t)n * 128 + c] = (t[h] - mu) * rs * g1[c] + be1[c];
    }
}

// ---------------- launch ----------------
extern "C" void kernel_launch(void* const* d_in, const int* in_sizes, int n_in,
                              void* d_out, int out_size)
{
    const float* x   = (const float*)d_in[0];
    const int*   nbr = (const int*)  d_in[1];
    const float* wq  = (const float*)d_in[2];
    const float* wk  = (const float*)d_in[3];
    const float* wv  = (const float*)d_in[4];
    const float* W1  = (const float*)d_in[5];
    const float* b1  = (const float*)d_in[6];
    const float* W2  = (const float*)d_in[7];
    const float* b2  = (const float*)d_in[8];
    const float* g1  = (const float*)d_in[9];
    const float* be1 = (const float*)d_in[10];
    const float* g2  = (const float*)d_in[11];
    const float* be2 = (const float*)d_in[12];
    float* out = (float*)d_out;

    void *pQ, *pK, *pV, *pH, *pF;
    cudaGetSymbolAddress(&pQ, g_Q);
    cudaGetSymbolAddress(&pK, g_K);
    cudaGetSymbolAddress(&pV, g_V);
    cudaGetSymbolAddress(&pH, g_H);
    cudaGetSymbolAddress(&pF, g_F);

    const size_t SM_AB = (size_t)(32 * 132 + 32 * 128) * sizeof(float);   // 33.3 KB
    const size_t SM_C  = (size_t)(128 * 132) * sizeof(float);             // 67.6 KB
    cudaFuncSetAttribute((const void*)gemm_kernel,
                         cudaFuncAttributeMaxDynamicSharedMemorySize, (int)SM_C);

    const int GN = (NN + 127) / 128;   // 782

    zero_denoms_kernel<<<1, 32>>>();

    // Q = x @ Wq      (cols = h*32+k)
    gemm_kernel<<<dim3(GN, 1, 1), 256, SM_AB>>>(
        x, 128, nullptr, wq, 4096, 32, 0, 4,
        (float*)pQ, 128, 0, 0, nullptr, nullptr, nullptr, nullptr);

    // K_r = x_nb[:,r] @ Wk[:,r]   for r = 0..4 (z-dim)
    gemm_kernel<<<dim3(GN, 1, 5), 256, SM_AB>>>(
        x, 128, nbr, wk, 20480, 32, 4096, 4,
        (float*)pK, 128, (size_t)NN * 128, 0, nullptr, nullptr, nullptr, nullptr);

    // V_r = x_nb[:,r] @ Wv[:,r]
    gemm_kernel<<<dim3(GN, 1, 5), 256, SM_AB>>>(
        x, 128, nbr, wv, 20480, 32, 4096, 4,
        (float*)pV, 128, (size_t)NN * 128, 0, nullptr, nullptr, nullptr, nullptr);

    // logits + global softmax denominators (softmax over the NODE axis)
    logits_kernel<<<NN / 8, 256>>>();

    // combine + residual + LN1 -> g_H
    combine_ln1_kernel<<<NN / 8, 256>>>(x, g1, be1);

    // FFN1: relu(g_H @ W1 + b1) -> g_F
    gemm_kernel<<<dim3(GN, 4, 1), 256, SM_AB>>>(
        (const float*)pH, 128, nullptr, W1, 32, 512, 0, 4,
        (float*)pF, 512, 0, 1, b1, nullptr, nullptr, nullptr);

    // FFN2 + residual + LN2 -> out
    gemm_kernel<<<dim3(GN, 1, 1), 256, SM_C>>>(
        (const float*)pF, 512, nullptr, W2, 32, 128, 0, 16,
        out, 128, 0, 2, b2, (const float*)pH, g2, be2);
}

// round 4
// speedup vs baseline: 1.3864x; 1.3864x over previous
#include <cuda_runtime.h>
#include <cstdint>
#include <math.h>

#define NN 100000

// ---------------- scratch ----------------
__device__ float g_Q[(size_t)NN * 128];
__device__ float g_K[(size_t)5 * NN * 128];
__device__ float g_V[(size_t)5 * NN * 128];
__device__ float g_E[(size_t)NN * 20];
__device__ float g_H[(size_t)NN * 128];
__device__ float g_F[(size_t)NN * 512];
__device__ float g_denom[20];

__device__ __forceinline__ uint32_t f2tf(float f) {
    uint32_t u; asm("cvt.rna.tf32.f32 %0, %1;" : "=r"(u) : "f"(f)); return u;
}

__global__ void zero_denoms_kernel() {
    if (threadIdx.x < 20) g_denom[threadIdx.x] = 0.0f;
}

// ---------------- tf32 mma.sync GEMM, 128x128 CTA tile ----------------
// C[gr, cg] = sum_k A[rowmap(gr), k] * B[k, cg]
// B element (k, c): Bbase + z*BzStride + (c>>5)*HS + k*KS + (c&31)
// epi: 0 plain, 1 bias+relu, 2 bias+resid+LayerNorm
__global__ __launch_bounds__(256, 2)
void tgemm(const float* __restrict__ A, int Astride,
           const int* __restrict__ nbr,
           const float* __restrict__ Bbase, int HS, int KS, int BzStride,
           int kchunks,
           float* __restrict__ C, int Cstride, size_t CzStride,
           int epi,
           const float* __restrict__ bias,
           const float* __restrict__ resid,
           const float* __restrict__ gamma,
           const float* __restrict__ beta)
{
    extern __shared__ uint32_t sm[];
    uint32_t* sA = sm;            // [32][132] k-major tf32 bits
    uint32_t* sB = sm + 32*132;   // [32][132]
    __shared__ int rowg[128];

    const int tid  = threadIdx.x;
    const int wid  = tid >> 5;
    const int lane = tid & 31;
    const int g4   = lane >> 2;   // group id 0..7
    const int t4   = lane & 3;    // thread-in-group
    const int z    = blockIdx.z;
    const int cg0  = blockIdx.y * 128;
    const int m0   = blockIdx.x * 128;
    const int m0w  = (wid >> 1) * 32;   // warp m offset in tile
    const int n0w  = (wid & 1) * 64;    // warp n offset in tile
    const float* Bp = Bbase + (size_t)z * BzStride;
    float*       Cp = C + (size_t)z * CzStride;

    if (tid < 128) {
        int gr  = m0 + tid;
        int idx = (gr < NN) ? gr : (NN - 1);
        if (nbr != nullptr && z > 0 && gr < NN) idx = nbr[gr * 4 + (z - 1)];
        rowg[tid] = idx;
    }
    __syncthreads();

    float d[2][8][4];
#pragma unroll
    for (int i = 0; i < 2; i++)
#pragma unroll
        for (int j = 0; j < 8; j++)
#pragma unroll
            for (int q = 0; q < 4; q++) d[i][j][q] = 0.0f;

    for (int kc = 0; kc < kchunks; ++kc) {
        const int kg0 = kc * 32;
        // A tile: 128 rows x 32 k -> k-major tf32
#pragma unroll
        for (int p = 0; p < 4; ++p) {
            int idx = tid + p * 256;
            int row = idx >> 3;
            int kq  = (idx & 7) << 2;
            const float* src = A + (size_t)rowg[row] * Astride + kg0 + kq;
            float4 v = *(const float4*)src;
            sA[(kq + 0) * 132 + row] = f2tf(v.x);
            sA[(kq + 1) * 132 + row] = f2tf(v.y);
            sA[(kq + 2) * 132 + row] = f2tf(v.z);
            sA[(kq + 3) * 132 + row] = f2tf(v.w);
        }
        // B tile: 32 k x 128 c
#pragma unroll
        for (int p = 0; p < 4; ++p) {
            int i  = tid + p * 256;
            int kl = i >> 5;
            int c  = (i & 31) << 2;
            int cg = cg0 + c;
            const float* src = Bp + (size_t)(cg >> 5) * HS + (size_t)(kg0 + kl) * KS + (cg & 31);
            float4 v = *(const float4*)src;
            uint4 t = make_uint4(f2tf(v.x), f2tf(v.y), f2tf(v.z), f2tf(v.w));
            *(uint4*)(sB + kl * 132 + c) = t;
        }
        __syncthreads();
#pragma unroll
        for (int ks = 0; ks < 4; ++ks) {
            const int kk = ks * 8;
            uint32_t a[2][4], b[8][2];
#pragma unroll
            for (int mf = 0; mf < 2; ++mf) {
                int r = m0w + mf * 16 + g4;
                a[mf][0] = sA[(kk + t4) * 132 + r];
                a[mf][1] = sA[(kk + t4) * 132 + r + 8];
                a[mf][2] = sA[(kk + 4 + t4) * 132 + r];
                a[mf][3] = sA[(kk + 4 + t4) * 132 + r + 8];
            }
#pragma unroll
            for (int nf = 0; nf < 8; ++nf) {
                int c = n0w + nf * 8 + g4;
                b[nf][0] = sB[(kk + t4) * 132 + c];
                b[nf][1] = sB[(kk + 4 + t4) * 132 + c];
            }
#pragma unroll
            for (int mf = 0; mf < 2; ++mf)
#pragma unroll
                for (int nf = 0; nf < 8; ++nf)
                    asm volatile(
                        "mma.sync.aligned.m16n8k8.row.col.f32.tf32.tf32.f32 "
                        "{%0,%1,%2,%3}, {%4,%5,%6,%7}, {%8,%9}, {%0,%1,%2,%3};"
                        : "+f"(d[mf][nf][0]), "+f"(d[mf][nf][1]),
                          "+f"(d[mf][nf][2]), "+f"(d[mf][nf][3])
                        : "r"(a[mf][0]), "r"(a[mf][1]), "r"(a[mf][2]), "r"(a[mf][3]),
                          "r"(b[nf][0]), "r"(b[nf][1]));
        }
        __syncthreads();
    }

    // ---- stage accumulators into padded smem [128][132] (reuses sA/sB region)
    float* sC = (float*)sm;
#pragma unroll
    for (int mf = 0; mf < 2; ++mf)
#pragma unroll
        for (int nf = 0; nf < 8; ++nf) {
            int row = m0w + mf * 16 + g4;
            int col = n0w + nf * 8 + t4 * 2;
            *(float2*)(sC + row * 132 + col)       = make_float2(d[mf][nf][0], d[mf][nf][1]);
            *(float2*)(sC + (row + 8) * 132 + col) = make_float2(d[mf][nf][2], d[mf][nf][3]);
        }
    __syncthreads();

    if (epi == 2) {
        // bias + resid + row LayerNorm (full row in this block: cg0==0, Cstride==128)
        for (int rr = wid; rr < 128; rr += 8) {
            int gr = m0 + rr;
            if (gr >= NN) continue;
            const float* rp = resid + (size_t)gr * 128;
            float v0 = sC[rr * 132 + lane]      + bias[lane]      + rp[lane];
            float v1 = sC[rr * 132 + 32 + lane] + bias[32 + lane] + rp[32 + lane];
            float v2 = sC[rr * 132 + 64 + lane] + bias[64 + lane] + rp[64 + lane];
            float v3 = sC[rr * 132 + 96 + lane] + bias[96 + lane] + rp[96 + lane];
            float s1 = v0 + v1 + v2 + v3;
            float s2 = v0 * v0 + v1 * v1 + v2 * v2 + v3 * v3;
#pragma unroll
            for (int o = 16; o > 0; o >>= 1) {
                s1 += __shfl_xor_sync(0xffffffffu, s1, o);
                s2 += __shfl_xor_sync(0xffffffffu, s2, o);
            }
            float mu  = s1 * (1.0f / 128.0f);
            float var = s2 * (1.0f / 128.0f) - mu * mu;
            float rs  = rsqrtf(var + 1e-5f);
            float* dst = Cp + (size_t)gr * 128;
            dst[lane]      = (v0 - mu) * rs * gamma[lane]      + beta[lane];
            dst[lane + 32] = (v1 - mu) * rs * gamma[lane + 32] + beta[lane + 32];
            dst[lane + 64] = (v2 - mu) * rs * gamma[lane + 64] + beta[lane + 64];
            dst[lane + 96] = (v3 - mu) * rs * gamma[lane + 96] + beta[lane + 96];
        }
    } else {
        // each row covered by 8 threads (i&7); each stores 16 contiguous floats
#pragma unroll
        for (int p = 0; p < 4; ++p) {
            int i   = tid + p * 256;
            int row = i >> 3;
            int q   = (i & 7) << 4;          // col base: 0,16,...,112
            int gr  = m0 + row;
            if (gr >= NN) continue;
#pragma unroll
            for (int h = 0; h < 4; ++h) {
                int c  = q + h * 4;
                float4 v = *(const float4*)(sC + row * 132 + c);
                int cg = cg0 + c;
                if (epi == 1) {
                    v.x = fmaxf(v.x + bias[cg + 0], 0.f);
                    v.y = fmaxf(v.y + bias[cg + 1], 0.f);
                    v.z = fmaxf(v.z + bias[cg + 2], 0.f);
                    v.w = fmaxf(v.w + bias[cg + 3], 0.f);
                }
                *(float4*)(Cp + (size_t)gr * Cstride + cg) = v;
            }
        }
    }
}

// ---------------- logits ----------------
__global__ void logits_kernel() {
    __shared__ float sden[20];
    const int tid = threadIdx.x;
    if (tid < 20) sden[tid] = 0.0f;
    __syncthreads();
    const int n    = blockIdx.x * 8 + (tid >> 5);
    const int lane = tid & 31;
    if (n < NN) {
        const float scale = 0.1767766952966369f;
#pragma unroll
        for (int h = 0; h < 4; h++) {
            float q = g_Q[(size_t)n * 128 + h * 32 + lane];
#pragma unroll
            for (int r = 0; r < 5; r++) {
                float s = q * g_K[((size_t)r * NN + n) * 128 + h * 32 + lane];
#pragma unroll
                for (int o = 16; o > 0; o >>= 1) s += __shfl_xor_sync(0xffffffffu, s, o);
                float e = expf(s * scale);
                if (lane == 0) {
                    g_E[(size_t)n * 20 + h * 5 + r] = e;
                    atomicAdd(&sden[h * 5 + r], e);
                }
            }
        }
    }
    __syncthreads();
    if (tid < 20) atomicAdd(&g_denom[tid], sden[tid]);
}

// ---------------- combine + residual + LN1 ----------------
__global__ void combine_ln1_kernel(const float* __restrict__ x,
                                   const float* __restrict__ g1,
                                   const float* __restrict__ be1) {
    __shared__ float sinv[20];
    const int tid = threadIdx.x;
    if (tid < 20) sinv[tid] = 1.0f / g_denom[tid];
    __syncthreads();
    const int n    = blockIdx.x * 8 + (tid >> 5);
    const int lane = tid & 31;
    if (n >= NN) return;
    float t[4];
    float s1 = 0.0f, s2 = 0.0f;
#pragma unroll
    for (int h = 0; h < 4; h++) {
        float z = 0.0f;
#pragma unroll
        for (int r = 0; r < 5; r++) {
            float p = g_E[(size_t)n * 20 + h * 5 + r] * sinv[h * 5 + r];
            z = fmaf(p, g_V[((size_t)r * NN + n) * 128 + h * 32 + lane], z);
        }
        float v = x[(size_t)n * 128 + h * 32 + lane] + z;
        t[h] = v;
        s1 += v;
        s2 = fmaf(v, v, s2);
    }
#pragma unroll
    for (int o = 16; o > 0; o >>= 1) {
        s1 += __shfl_xor_sync(0xffffffffu, s1, o);
        s2 += __shfl_xor_sync(0xffffffffu, s2, o);
    }
    float mu  = s1 * (1.0f / 128.0f);
    float var = s2 * (1.0f / 128.0f) - mu * mu;
    float rs  = rsqrtf(var + 1e-5f);
#pragma unroll
    for (int h = 0; h < 4; h++) {
        int c = h * 32 + lane;
        g_H[(size_t)n * 128 + c] = (t[h] - mu) * rs * g1[c] + be1[c];
    }
}

// ---------------- launch ----------------
extern "C" void kernel_launch(void* const* d_in, const int* in_sizes, int n_in,
                              void* d_out, int out_size)
{
    const float* x   = (const float*)d_in[0];
    const int*   nbr = (const int*)  d_in[1];
    const float* wq  = (const float*)d_in[2];
    const float* wk  = (const float*)d_in[3];
    const float* wv  = (const float*)d_in[4];
    const float* W1  = (const float*)d_in[5];
    const float* b1  = (const float*)d_in[6];
    const float* W2  = (const float*)d_in[7];
    const float* b2  = (const float*)d_in[8];
    const float* g1  = (const float*)d_in[9];
    const float* be1 = (const float*)d_in[10];
    const float* g2  = (const float*)d_in[11];
    const float* be2 = (const float*)d_in[12];
    float* out = (float*)d_out;

    void *pQ, *pK, *pV, *pH, *pF;
    cudaGetSymbolAddress(&pQ, g_Q);
    cudaGetSymbolAddress(&pK, g_K);
    cudaGetSymbolAddress(&pV, g_V);
    cudaGetSymbolAddress(&pH, g_H);
    cudaGetSymbolAddress(&pF, g_F);

    const size_t SMEMSZ = (size_t)128 * 132 * sizeof(float);   // 67584
    cudaFuncSetAttribute((const void*)tgemm,
                         cudaFuncAttributeMaxDynamicSharedMemorySize, (int)SMEMSZ);

    const int GN = (NN + 127) / 128;   // 782

    zero_denoms_kernel<<<1, 32>>>();

    // Q = x @ Wq
    tgemm<<<dim3(GN, 1, 1), 256, SMEMSZ>>>(
        x, 128, nullptr, wq, 4096, 32, 0, 4,
        (float*)pQ, 128, 0, 0, nullptr, nullptr, nullptr, nullptr);

    // K_r = x_nb[:,r] @ Wk[:,r]
    tgemm<<<dim3(GN, 1, 5), 256, SMEMSZ>>>(
        x, 128, nbr, wk, 20480, 32, 4096, 4,
        (float*)pK, 128, (size_t)NN * 128, 0, nullptr, nullptr, nullptr, nullptr);

    // V_r
    tgemm<<<dim3(GN, 1, 5), 256, SMEMSZ>>>(
        x, 128, nbr, wv, 20480, 32, 4096, 4,
        (float*)pV, 128, (size_t)NN * 128, 0, nullptr, nullptr, nullptr, nullptr);

    logits_kernel<<<NN / 8, 256>>>();
    combine_ln1_kernel<<<NN / 8, 256>>>(x, g1, be1);

    // FFN1: relu(H @ W1 + b1)
    tgemm<<<dim3(GN, 4, 1), 256, SMEMSZ>>>(
        (const float*)pH, 128, nullptr, W1, 32, 512, 0, 4,
        (float*)pF, 512, 0, 1, b1, nullptr, nullptr, nullptr);

    // FFN2 + resid + LN2
    tgemm<<<dim3(GN, 1, 1), 256, SMEMSZ>>>(
        (const float*)pF, 512, nullptr, W2, 32, 128, 0, 16,
        out, 128, 0, 2, b2, (const float*)pH, g2, be2);
}